// round 5
// baseline (speedup 1.0000x reference)
#include <cuda_runtime.h>
#include <cuda_bf16.h>
#include <stdint.h>

// Problem constants (fixed by the dataset):
//   x:          (80, 2048, 16, 16) f32
//   s_ca:       (80, 2048, 1, 1)   f32
//   rand_index: (80, 512)          int32
//   partner:    (80,)              int32
//   out:        (160, 2048, 16, 16) f32
#define NB    80
#define CCH   2048
#define NQ    64        // 16*16/4 float4 per channel
#define SSH   512
#define NBUCK 2048
#define CPB   64        // channels per block
#define TPB   256

// ---------------------------------------------------------------------------
// One fused kernel. Block (m, n) owns row n, channels [m*64, m*64+64).
//
// Rank phase (O(c) per block): scores ~ U[0,1), bucket = min(int(v*2048),
// 2047) is monotone (×2048 is exact). Histogram -> descending prefix ->
// counting-sort scatter of ids -> exact rank via within-bucket refinement
// with jax top_k's stable tie-break (s_i > s_ch, or equal and i < ch).
// rank < 512 <=> channel is in top_k at list position k = rank.
//
// Memory phase: 64 ch x 64 quads = 4096 float4 tasks, 16/thread, coalesced.
// Both output halves produced from a single x read.
// ---------------------------------------------------------------------------
__global__ void __launch_bounds__(TPB, 8)
fused_kernel(const float* __restrict__ x,
             const float* __restrict__ s_ca,
             const int*   __restrict__ rand_index,
             const int*   __restrict__ partner,
             float*       __restrict__ out)
{
    __shared__ float          ss[CCH];       // score row
    __shared__ int            hcnt[NBUCK];   // histogram, then scatter cursor
    __shared__ unsigned short off[NBUCK];    // # elements in strictly higher buckets
    __shared__ unsigned short sidx[CCH];     // ids grouped by bucket (desc)
    __shared__ int            wsum[TPB / 32];
    __shared__ short          srank[CPB];

    const int n    = blockIdx.y;
    const int ch0  = blockIdx.x * CPB;
    const int t    = threadIdx.x;
    const int lane = t & 31;
    const int w    = t >> 5;

    const float* row = s_ca + (size_t)n * CCH;

    // Load scores + zero histogram
#pragma unroll
    for (int i = t; i < CCH; i += TPB) { ss[i] = row[i]; hcnt[i] = 0; }
    __syncthreads();

    // Histogram
#pragma unroll
    for (int i = t; i < CCH; i += TPB) {
        int bkt = (int)(ss[i] * (float)NBUCK);
        bkt = bkt > NBUCK - 1 ? NBUCK - 1 : bkt;
        atomicAdd(&hcnt[bkt], 1);
    }
    __syncthreads();

    // Ascending prefix -> off[b] = CCH - inclusive_prefix(b). Thread t owns
    // bins [8t, 8t+8).
    {
        int loc[8]; int sum = 0;
#pragma unroll
        for (int i = 0; i < 8; ++i) { loc[i] = hcnt[8 * t + i]; sum += loc[i]; }
        int incl = sum;
#pragma unroll
        for (int o = 1; o < 32; o <<= 1) {
            int v = __shfl_up_sync(0xFFFFFFFFu, incl, o);
            if (lane >= o) incl += v;
        }
        if (lane == 31) wsum[w] = incl;
        __syncthreads();
        int base = 0;
#pragma unroll
        for (int i = 0; i < TPB / 32; ++i) base += (i < w) ? wsum[i] : 0;
        int run = base + incl - sum;         // exclusive prefix before bin 8t
#pragma unroll
        for (int i = 0; i < 8; ++i) {
            run += loc[i];                   // inclusive through bin 8t+i
            off[8 * t + i] = (unsigned short)(CCH - run);
        }
    }
    __syncthreads();

    // Reset cursors
#pragma unroll
    for (int i = t; i < NBUCK; i += TPB) hcnt[i] = 0;
    __syncthreads();

    // Scatter ids grouped by bucket
#pragma unroll
    for (int i = t; i < CCH; i += TPB) {
        int bkt = (int)(ss[i] * (float)NBUCK);
        bkt = bkt > NBUCK - 1 ? NBUCK - 1 : bkt;
        int p = off[bkt] + atomicAdd(&hcnt[bkt], 1);
        sidx[p] = (unsigned short)i;
    }
    __syncthreads();

    // Exact rank for this block's 64 channels.
    // Bucket b occupies sidx[off[b] .. off[b-1]) (off[-1] == CCH).
    if (t < CPB) {
        const int ch = ch0 + t;
        const float v = ss[ch];
        int bkt = (int)(v * (float)NBUCK);
        bkt = bkt > NBUCK - 1 ? NBUCK - 1 : bkt;
        const int s_ = off[bkt];
        const int e_ = (bkt > 0) ? (int)off[bkt - 1] : CCH;
        int r = s_;
        for (int p = s_; p < e_; ++p) {
            int i = sidx[p];
            float u = ss[i];
            r += (u > v) || (u == v && i < ch);
        }
        srank[t] = (short)r;
    }
    __syncthreads();

    // Memory phase
    const int vway = n >> 4;
    const int bslt = n & 15;
    const int jrow = (n + 1 + __ldg(&partner[n])) % NB;

    const float4* x4 = (const float4*)x;
    float4*       o4 = (float4*)out;

#pragma unroll
    for (int it = 0; it < (CPB * NQ) / TPB; ++it) {
        const int task = it * TPB + t;       // 0..4095
        const int ci   = task >> 6;          // channel within block
        const int q    = task & 63;          // float4 quad within channel
        const int ch   = ch0 + ci;
        const float s  = ss[ch];

        float4 xv = x4[((size_t)n * CCH + ch) * NQ + q];

        float4 po;
        po.x = xv.x * s; po.y = xv.y * s; po.z = xv.z * s; po.w = xv.w * s;
        o4[(((size_t)(vway * 32 + bslt)) * CCH + ch) * NQ + q] = po;

        float4 ao = po;
        const int k = srank[ci];             // uniform across the warp
        if (k < SSH) {
            int rc = __ldg(&rand_index[n * SSH + k]);
            float4 pv = x4[((size_t)jrow * CCH + rc) * NQ + q];
            ao.x = (0.7f * xv.x + 0.3f * pv.x) * s;
            ao.y = (0.7f * xv.y + 0.3f * pv.y) * s;
            ao.z = (0.7f * xv.z + 0.3f * pv.z) * s;
            ao.w = (0.7f * xv.w + 0.3f * pv.w) * s;
        }
        o4[(((size_t)(vway * 32 + 16 + bslt)) * CCH + ch) * NQ + q] = ao;
    }
}

extern "C" void kernel_launch(void* const* d_in, const int* in_sizes, int n_in,
                              void* d_out, int out_size)
{
    const float* x          = (const float*)d_in[0];
    const float* s_ca       = (const float*)d_in[1];
    const int*   rand_index = (const int*)  d_in[2];
    const int*   partner    = (const int*)  d_in[3];
    float*       out        = (float*)d_out;

    dim3 blk(TPB);
    dim3 grd(CCH / CPB, NB);   // (32, 80)
    fused_kernel<<<grd, blk>>>(x, s_ca, rand_index, partner, out);
}

// round 6
// speedup vs baseline: 1.1618x; 1.1618x over previous
#include <cuda_runtime.h>
#include <cuda_bf16.h>
#include <stdint.h>

// Problem constants (fixed by the dataset):
//   x:          (80, 2048, 16, 16) f32
//   s_ca:       (80, 2048, 1, 1)   f32
//   rand_index: (80, 512)          int32
//   partner:    (80,)              int32
//   out:        (160, 2048, 16, 16) f32
#define NB    80
#define CCH   2048
#define NQ    64        // 16*16/4 float4 per channel
#define SSH   512
#define NBUCK 2048
#define CPB   64        // channels per block
#define TPB   256

// ---------------------------------------------------------------------------
// One fused kernel. Block (m, n) owns row n, channels [m*64, m*64+64).
// Rank phase: O(c) bucket counting sort (scores ~ U[0,1), bucket map is
// monotone), exact jax top_k stable ordering via within-bucket refinement.
// Memory phase: 8-deep batched float4 loads (4 xv + 4 predicated partner pv)
// per group to maximize MLP; both output halves from one x read.
// ---------------------------------------------------------------------------
__global__ void __launch_bounds__(TPB, 4)
fused_kernel(const float* __restrict__ x,
             const float* __restrict__ s_ca,
             const int*   __restrict__ rand_index,
             const int*   __restrict__ partner,
             float*       __restrict__ out)
{
    __shared__ float          ss[CCH];       // score row
    __shared__ int            hcnt[NBUCK];   // histogram, then scatter cursor
    __shared__ unsigned short off[NBUCK];    // # elements in strictly higher buckets
    __shared__ unsigned short sidx[CCH];     // ids grouped by bucket (desc)
    __shared__ int            wsum[TPB / 32];
    __shared__ short          srank[CPB];

    const int n    = blockIdx.y;
    const int ch0  = blockIdx.x * CPB;
    const int t    = threadIdx.x;
    const int lane = t & 31;
    const int w    = t >> 5;

    const float* row = s_ca + (size_t)n * CCH;

    // Load scores + zero histogram
#pragma unroll
    for (int i = t; i < CCH; i += TPB) { ss[i] = row[i]; hcnt[i] = 0; }
    __syncthreads();

    // Histogram
#pragma unroll
    for (int i = t; i < CCH; i += TPB) {
        int bkt = (int)(ss[i] * (float)NBUCK);
        bkt = bkt > NBUCK - 1 ? NBUCK - 1 : bkt;
        atomicAdd(&hcnt[bkt], 1);
    }
    __syncthreads();

    // Ascending prefix -> off[b] = CCH - inclusive_prefix(b). Thread t owns
    // bins [8t, 8t+8).
    {
        int loc[8]; int sum = 0;
#pragma unroll
        for (int i = 0; i < 8; ++i) { loc[i] = hcnt[8 * t + i]; sum += loc[i]; }
        int incl = sum;
#pragma unroll
        for (int o = 1; o < 32; o <<= 1) {
            int v = __shfl_up_sync(0xFFFFFFFFu, incl, o);
            if (lane >= o) incl += v;
        }
        if (lane == 31) wsum[w] = incl;
        __syncthreads();
        int base = 0;
#pragma unroll
        for (int i = 0; i < TPB / 32; ++i) base += (i < w) ? wsum[i] : 0;
        int run = base + incl - sum;         // exclusive prefix before bin 8t
#pragma unroll
        for (int i = 0; i < 8; ++i) {
            run += loc[i];                   // inclusive through bin 8t+i
            off[8 * t + i] = (unsigned short)(CCH - run);
        }
    }
    __syncthreads();

    // Reset cursors
#pragma unroll
    for (int i = t; i < NBUCK; i += TPB) hcnt[i] = 0;
    __syncthreads();

    // Scatter ids grouped by bucket
#pragma unroll
    for (int i = t; i < CCH; i += TPB) {
        int bkt = (int)(ss[i] * (float)NBUCK);
        bkt = bkt > NBUCK - 1 ? NBUCK - 1 : bkt;
        int p = off[bkt] + atomicAdd(&hcnt[bkt], 1);
        sidx[p] = (unsigned short)i;
    }
    __syncthreads();

    // Exact rank for this block's 64 channels.
    if (t < CPB) {
        const int ch = ch0 + t;
        const float v = ss[ch];
        int bkt = (int)(v * (float)NBUCK);
        bkt = bkt > NBUCK - 1 ? NBUCK - 1 : bkt;
        const int s_ = off[bkt];
        const int e_ = (bkt > 0) ? (int)off[bkt - 1] : CCH;
        int r = s_;
        for (int p = s_; p < e_; ++p) {
            int i = sidx[p];
            float u = ss[i];
            r += (u > v) || (u == v && i < ch);
        }
        srank[t] = (short)r;
    }
    __syncthreads();

    // ------------------------- Memory phase -------------------------
    const int vway = n >> 4;
    const int bslt = n & 15;
    const int jrow = (n + 1 + __ldg(&partner[n])) % NB;

    const float4* x4 = (const float4*)x;
    float4*       o4 = (float4*)out;

    const int qq    = t & 63;     // float4 quad within channel (fixed)
    const int cbase = t >> 6;     // 0..3

    const float4* xrow = x4 + (size_t)n    * CCH * NQ + qq;
    const float4* jrw  = x4 + (size_t)jrow * CCH * NQ + qq;
    float4* oplain = o4 + ((size_t)(vway * 32 + bslt))      * CCH * NQ + qq;
    float4* oaug   = o4 + ((size_t)(vway * 32 + 16 + bslt)) * CCH * NQ + qq;

#pragma unroll
    for (int g = 0; g < 4; ++g) {
        int   ch[4];
        int   kk[4];
        float4 xv[4];
        float4 pv[4];

        // Batch 1: 4 xv loads + 4 predicated partner loads, all independent.
#pragma unroll
        for (int i = 0; i < 4; ++i) {
            const int ci = cbase + 4 * (4 * g + i);
            ch[i] = ch0 + ci;
            xv[i] = xrow[(size_t)ch[i] * NQ];
            kk[i] = srank[ci];                       // warp-uniform
        }
#pragma unroll
        for (int i = 0; i < 4; ++i) {
            if (kk[i] < SSH) {
                int rc = __ldg(&rand_index[n * SSH + kk[i]]);
                pv[i] = jrw[(size_t)rc * NQ];
            }
        }

        // Batch 2: compute + store.
#pragma unroll
        for (int i = 0; i < 4; ++i) {
            const float s = ss[ch[i]];
            float4 po;
            po.x = xv[i].x * s; po.y = xv[i].y * s;
            po.z = xv[i].z * s; po.w = xv[i].w * s;
            oplain[(size_t)ch[i] * NQ] = po;

            float4 ao = po;
            if (kk[i] < SSH) {
                ao.x = (0.7f * xv[i].x + 0.3f * pv[i].x) * s;
                ao.y = (0.7f * xv[i].y + 0.3f * pv[i].y) * s;
                ao.z = (0.7f * xv[i].z + 0.3f * pv[i].z) * s;
                ao.w = (0.7f * xv[i].w + 0.3f * pv[i].w) * s;
            }
            oaug[(size_t)ch[i] * NQ] = ao;
        }
    }
}

extern "C" void kernel_launch(void* const* d_in, const int* in_sizes, int n_in,
                              void* d_out, int out_size)
{
    const float* x          = (const float*)d_in[0];
    const float* s_ca       = (const float*)d_in[1];
    const int*   rand_index = (const int*)  d_in[2];
    const int*   partner    = (const int*)  d_in[3];
    float*       out        = (float*)d_out;

    dim3 blk(TPB);
    dim3 grd(CCH / CPB, NB);   // (32, 80)
    fused_kernel<<<grd, blk>>>(x, s_ca, rand_index, partner, out);
}